// round 14
// baseline (speedup 1.0000x reference)
#include <cuda_runtime.h>
#include <cuda_fp16.h>
#include <math.h>
#include <stdint.h>

#define T_STEPS 50
#define BB      1024
#define S_DIM   32
#define D_DIM   600
#define H_DIM   600
#define A_DIM   6
#define E_DIM   1024
#define G3_DIM  1800
#define MIN_STD 0.1f
#define KSPLIT  5
#define MAXCTA  304

#define SZ_SB   ((size_t)T_STEPS * BB * S_DIM)
#define SZ_DB   ((size_t)T_STEPS * BB * D_DIM)
#define OFF_PM    ((size_t)0)
#define OFF_PS    (SZ_SB)
#define OFF_PRIOR (2 * SZ_SB)
#define OFF_DET1  (3 * SZ_SB)
#define OFF_QM    (3 * SZ_SB + SZ_DB)
#define OFF_QS    (4 * SZ_SB + SZ_DB)
#define OFF_POST  (5 * SZ_SB + SZ_DB)
#define OFF_DET2  (6 * SZ_SB + SZ_DB)

// ---------------- static device scratch ----------------
__device__ __half g_Wih[G3_DIM * D_DIM];
__device__ __half g_Whh[G3_DIM * D_DIM];
__device__ __half g_Wp1[H_DIM * D_DIM];
__device__ __half g_Wq1d[H_DIM * D_DIM];
__device__ __half g_Wq1e[H_DIM * E_DIM];
__device__ __half g_Wp2[64 * H_DIM];
__device__ __half g_Wq2[64 * H_DIM];
__device__ __half g_enc_h[(size_t)T_STEPS * BB * E_DIM];
__device__ __half g_enc_l[(size_t)T_STEPS * BB * E_DIM];
__device__ float  g_genc[(size_t)T_STEPS * BB * D_DIM];
__device__ __half g_rnn_h[BB * H_DIM], g_rnn_l[BB * H_DIM];
__device__ __half g_det_h[BB * D_DIM], g_det_l[BB * D_DIM];
__device__ __half g_hp_h [BB * H_DIM], g_hp_l [BB * H_DIM];
__device__ __half g_hq_h [BB * H_DIM], g_hq_l [BB * H_DIM];
__device__ float g_gi[BB * G3_DIM], g_gh[BB * G3_DIM];
__device__ float g_hpart[2 * KSPLIT * BB * 64];

__device__ volatile unsigned g_flags[MAXCTA];
__device__ volatile unsigned g_go;
__device__ unsigned g_hcnt;
__device__ unsigned g_rcnt;

__device__ __forceinline__ float eluf(float x)      { return x > 0.f ? x : expm1f(x); }
__device__ __forceinline__ float sigmoidf_(float x) { return 1.f / (1.f + expf(-x)); }
__device__ __forceinline__ float softplusf_(float x){ return fmaxf(x, 0.f) + log1pf(expf(-fabsf(x))); }

// ---------------- PTX helpers ----------------
__device__ __forceinline__ uint32_t smem_u32(const void* p) {
    uint32_t a;
    asm("{ .reg .u64 t; cvta.to.shared.u64 t, %1; cvt.u32.u64 %0, t; }" : "=r"(a) : "l"(p));
    return a;
}
__device__ __forceinline__ void cpa16(uint32_t dst, const void* src, int nb) {
    asm volatile("cp.async.cg.shared.global [%0], [%1], 16, %2;" :: "r"(dst), "l"(src), "r"(nb));
}
#define CP_COMMIT() asm volatile("cp.async.commit_group;" ::: "memory")

__device__ __forceinline__ void ldsm4(uint32_t* r, uint32_t addr) {
    asm volatile("ldmatrix.sync.aligned.m8n8.x4.shared.b16 {%0,%1,%2,%3}, [%4];"
        : "=r"(r[0]), "=r"(r[1]), "=r"(r[2]), "=r"(r[3]) : "r"(addr));
}
__device__ __forceinline__ void mma16816(float* d, const uint32_t* a, const uint32_t* b) {
    asm volatile("mma.sync.aligned.m16n8k16.row.col.f32.f16.f16.f32 "
        "{%0,%1,%2,%3}, {%4,%5,%6,%7}, {%8,%9}, {%0,%1,%2,%3};"
        : "+f"(d[0]), "+f"(d[1]), "+f"(d[2]), "+f"(d[3])
        : "r"(a[0]), "r"(a[1]), "r"(a[2]), "r"(a[3]), "r"(b[0]), "r"(b[1]));
}

// ---------------- grid barrier / counter wait ----------------
__device__ __forceinline__ void gridbar(unsigned ph, int ncta) {
    __threadfence();
    __syncthreads();
    if (threadIdx.x == 0) g_flags[blockIdx.x] = ph;
    if (blockIdx.x == 0) {
        for (int c = threadIdx.x; c < ncta; c += 256)
            while (g_flags[c] < ph) { }
        __syncthreads();
        if (threadIdx.x == 0) { __threadfence(); g_go = ph; }
        __syncthreads();
    } else {
        if (threadIdx.x == 0) { while (g_go < ph) { } }
        __syncthreads();
    }
}
__device__ __forceinline__ void cnt_wait(unsigned* cnt, unsigned target) {
    if (threadIdx.x == 0) {
        while (*(volatile unsigned*)cnt < target) { }
    }
    __syncthreads();
    __threadfence();
}

// ---------------- GEMM tile: 2-term fp16, NP panels of 64 N each ----------------
#define BMT 128
#define RSB 144
#define ASZ (BMT * RSB)               // 18432
#define WSZ (64 * RSB)                // 9216
#define STG (2 * ASZ + 2 * WSZ)       // 55296 (max, NP=2)
#define SMEM_GEMM (2 * STG)           // 110592

template<int NP>
__device__ __forceinline__ void gemm_tile(
    const __half* Ahi, const __half* Alo, const __half* W,
    const float* bias, const float* extra,
    float* Cf, __half* Chi, __half* Clo,
    int N, int Kb, int KC, int m0, int n0, int koff, int elu, char* smraw)
{
    const int tid = threadIdx.x;
    const uint32_t sb = smem_u32(smraw);
    const int wid = tid >> 5, lane = tid & 31;
    const int wm = wid & 3, wn = wid >> 2;
    const int arow  = lane & 15;
    const int akoff = (lane >> 4) * 16;
    const int brow  = (lane & 7) + ((lane >> 4) << 3);
    const int bkoff = ((lane >> 3) & 1) * 16;
    constexpr int MYSTG = 2 * ASZ + NP * WSZ;

    float acc[NP][2][4][4];
#pragma unroll
    for (int p = 0; p < NP; p++)
#pragma unroll
        for (int i = 0; i < 2; i++)
#pragma unroll
            for (int j = 0; j < 4; j++)
#pragma unroll
                for (int q = 0; q < 4; q++) acc[p][i][j][q] = 0.f;

    auto load_stage = [&](int kc) {
        const uint32_t base = sb + (uint32_t)(kc & 1) * MYSTG;
        const int k0b = koff + kc * 128;
        #pragma unroll
        for (int v = 0; v < 8; v++) {                  // A hi|lo
            const int idx  = v * 256 + tid;
            const int half = idx >> 10, r = (idx >> 3) & 127, j = idx & 7;
            const int off  = k0b + j * 16;
            const char* src = (const char*)(half ? Alo : Ahi);
            const int nb = (off + 16 <= Kb) ? 16 : 0;
            const char* p = nb ? src + (size_t)(m0 + r) * Kb + off : src;
            cpa16(base + half * ASZ + r * RSB + j * 16, p, nb);
        }
        #pragma unroll
        for (int v = 0; v < 2 * NP; v++) {             // W panels: NP x 64 rows x 8 chunks
            const int idx = v * 256 + tid;
            const int pnl = idx >> 9;                  // 512 ops per panel
            const int r   = (idx >> 3) & 63, j = idx & 7;
            const int off = k0b + j * 16;
            const int gn  = n0 + pnl * 64 + r;
            const int nb  = (off + 16 <= Kb && gn < N) ? 16 : 0;
            const char* p = nb ? (const char*)W + (size_t)gn * Kb + off : (const char*)W;
            cpa16(base + 2 * ASZ + pnl * WSZ + r * RSB + j * 16, p, nb);
        }
        CP_COMMIT();
    };

    load_stage(0);
    for (int kc = 0; kc < KC; kc++) {
        if (kc + 1 < KC) { load_stage(kc + 1); asm volatile("cp.async.wait_group 1;" ::: "memory"); }
        else             {                      asm volatile("cp.async.wait_group 0;" ::: "memory"); }
        __syncthreads();
        const uint32_t base = sb + (uint32_t)(kc & 1) * MYSTG;

        #pragma unroll
        for (int k16 = 0; k16 < 4; k16++) {
            uint32_t a_h[2][4], a_l[2][4];
            const uint32_t Ah0 = base + (wm * 32 + arow) * RSB + k16 * 32 + akoff;
            ldsm4(a_h[0], Ah0);           ldsm4(a_h[1], Ah0 + 16 * RSB);
            ldsm4(a_l[0], Ah0 + ASZ);     ldsm4(a_l[1], Ah0 + ASZ + 16 * RSB);
            #pragma unroll
            for (int p = 0; p < NP; p++) {
                uint32_t b[2][4];
                const uint32_t Wh0 = base + 2 * ASZ + p * WSZ + (wn * 32 + brow) * RSB + k16 * 32 + bkoff;
                ldsm4(b[0], Wh0);         ldsm4(b[1], Wh0 + 16 * RSB);
                #pragma unroll
                for (int tm = 0; tm < 2; tm++)
                    #pragma unroll
                    for (int g = 0; g < 2; g++)
                        #pragma unroll
                        for (int sub = 0; sub < 2; sub++) {
                            float* d = acc[p][tm][g * 2 + sub];
                            mma16816(d, a_h[tm], &b[g][sub * 2]);
                            mma16816(d, a_l[tm], &b[g][sub * 2]);
                        }
            }
        }
        __syncthreads();
    }

    #pragma unroll
    for (int p = 0; p < NP; p++) {
        #pragma unroll
        for (int nt = 0; nt < 4; nt++) {
            const int gc = n0 + p * 64 + wn * 32 + nt * 8 + ((lane & 3) << 1);
            if (gc >= N) continue;
            const float b0 = bias ? bias[gc]     : 0.f;
            const float b1 = bias ? bias[gc + 1] : 0.f;
            #pragma unroll
            for (int tm = 0; tm < 2; tm++) {
                const int r0 = m0 + wm * 32 + tm * 16 + (lane >> 2);
                #pragma unroll
                for (int hh = 0; hh < 2; hh++) {
                    const int gr = r0 + hh * 8;
                    float v0 = acc[p][tm][nt][hh * 2 + 0] + b0;
                    float v1 = acc[p][tm][nt][hh * 2 + 1] + b1;
                    if (extra) {
                        v0 += extra[(size_t)gr * N + gc];
                        v1 += extra[(size_t)gr * N + gc + 1];
                    }
                    if (elu) { v0 = eluf(v0); v1 = eluf(v1); }
                    if (Cf) {
                        Cf[(size_t)gr * N + gc]     = v0;
                        Cf[(size_t)gr * N + gc + 1] = v1;
                    }
                    if (Chi) {
                        const __half h0 = __float2half(v0);
                        const __half h1 = __float2half(v1);
                        Chi[(size_t)gr * N + gc]     = h0;
                        Chi[(size_t)gr * N + gc + 1] = h1;
                        Clo[(size_t)gr * N + gc]     = __float2half(v0 - __half2float(h0));
                        Clo[(size_t)gr * N + gc + 1] = __float2half(v1 - __half2float(h1));
                    }
                }
            }
        }
    }
}

// ---------------- rnn compute ----------------
__device__ void rnn_compute(int b0, const float* __restrict__ W_in, const float* __restrict__ b_in,
                            float (*s_in)[38], __half* s_hi, __half* s_lo)
{
    const int tid = threadIdx.x;
    for (int h = tid; h < H_DIM; h += 256) {
        float w[38];
        #pragma unroll
        for (int k = 0; k < 38; k++) w[k] = W_in[h * 38 + k];
        const float bias = b_in[h];
        #pragma unroll 4
        for (int b = 0; b < 16; b++) {
            float acc = bias;
            #pragma unroll
            for (int k = 0; k < 38; k++) acc = fmaf(s_in[b][k], w[k], acc);
            const float v = eluf(acc);
            const __half hh = __float2half(v);
            s_hi[b * 600 + h] = hh;
            s_lo[b * 600 + h] = __float2half(v - __half2float(hh));
        }
    }
    __syncthreads();
    const size_t gbase = (size_t)b0 * H_DIM;
    for (int i = tid; i < 16 * 600; i += 256) {
        g_rnn_h[gbase + i] = s_hi[i];
        g_rnn_l[gbase + i] = s_lo[i];
    }
}

// gi/gh: N=1800, 15 n-blocks of 128, 8 m-blocks -> 120 tiles each
__device__ __forceinline__ void gi_tile(int u, const float* b_ih, char* smraw) {
    const int mb = u / 15, nb = u % 15;
    gemm_tile<2>(g_rnn_h, g_rnn_l, g_Wih, b_ih, nullptr,
                 g_gi, nullptr, nullptr, G3_DIM, 1200, 10, mb * 128, nb * 128, 0, 0, smraw);
}
__device__ __forceinline__ void gh_tile(int u, const float* b_hh, char* smraw) {
    const int mb = u / 15, nb = u % 15;
    gemm_tile<2>(g_det_h, g_det_l, g_Whh, b_hh, nullptr,
                 g_gh, nullptr, nullptr, G3_DIM, 1200, 10, mb * 128, nb * 128, 0, 0, smraw);
}

// ---------------- persistent rollout kernel ----------------
__global__ void __launch_bounds__(256, 2)
rssm_rollout(const float* __restrict__ actions, const float* __restrict__ init_stoch,
             const float* __restrict__ init_det,
             const float* __restrict__ noise_p, const float* __restrict__ noise_q,
             const float* __restrict__ W_in, const float* __restrict__ b_in,
             const float* __restrict__ b_ih, const float* __restrict__ b_hh,
             const float* __restrict__ bp1, const float* __restrict__ bq1,
             const float* __restrict__ bp2, const float* __restrict__ bq2,
             float* __restrict__ out, int ncta)
{
    extern __shared__ char smraw[];
    const int cta = blockIdx.x, tid = threadIdx.x;
    unsigned ph = g_go;
    const unsigned hbase = *(volatile unsigned*)&g_hcnt;
    const unsigned rbase = *(volatile unsigned*)&g_rcnt;

    float (*s_in)[38] = (float(*)[38])smraw;
    __half* s_hi = (__half*)(smraw + 4096);
    __half* s_lo = (__half*)(smraw + 4096 + 19200);

    // ---- preamble A: rnn(0) on CTAs<64; gh(0) on CTAs>=64 ----
    if (cta < 64) {
        const int b0 = cta * 16;
        for (int i = tid; i < 16 * 38; i += 256) {
            const int r = i / 38, k = i % 38;
            s_in[r][k] = (k < 6) ? actions[(size_t)(b0 + r) * A_DIM + k]
                                 : init_stoch[(size_t)(b0 + r) * S_DIM + (k - 6)];
        }
        __syncthreads();
        rnn_compute(b0, W_in, b_in, s_in, s_hi, s_lo);
    } else {
        for (int u = cta - 64; u < 120; u += ncta - 64) gh_tile(u, b_hh, smraw);
    }
    gridbar(++ph, ncta);

    // ---- preamble B: gi(0) ----
    for (int u = cta; u < 120; u += ncta) gi_tile(u, b_ih, smraw);
    gridbar(++ph, ncta);

    for (int t = 0; t < T_STEPS; t++) {
        const int last = (t + 1 == T_STEPS);

        // ---- P1: GRU gates ----
        {
            const float* det_prev = (t == 0) ? init_det : out + OFF_DET1 + (size_t)(t - 1) * BB * D_DIM;
            float* det1 = out + OFF_DET1 + (size_t)t * BB * D_DIM;
            float* det2 = out + OFF_DET2 + (size_t)t * BB * D_DIM;
            for (int q = cta * 256 + tid; q < BB * 150; q += ncta * 256) {
                const int b = q / 150, jq = (q % 150) * 4;
                const size_t gb = (size_t)b * G3_DIM + jq;
                const float4 ir = __ldcg((const float4*)(g_gi + gb));
                const float4 iz = __ldcg((const float4*)(g_gi + gb + D_DIM));
                const float4 in = __ldcg((const float4*)(g_gi + gb + 2 * D_DIM));
                const float4 hr = __ldcg((const float4*)(g_gh + gb));
                const float4 hz = __ldcg((const float4*)(g_gh + gb + D_DIM));
                const float4 hn = __ldcg((const float4*)(g_gh + gb + 2 * D_DIM));
                const size_t db = (size_t)b * D_DIM + jq;
                const float4 dp = __ldcg((const float4*)(det_prev + db));
                const float* pir = &ir.x; const float* piz = &iz.x; const float* pin = &in.x;
                const float* phr = &hr.x; const float* phz = &hz.x; const float* phn = &hn.x;
                const float* pdp = &dp.x;
                float d[4];
                #pragma unroll
                for (int u2 = 0; u2 < 4; u2++) {
                    const float r = sigmoidf_(pir[u2] + phr[u2]);
                    const float z = sigmoidf_(piz[u2] + phz[u2]);
                    const float n = tanhf(pin[u2] + r * phn[u2]);
                    d[u2] = (1.f - z) * n + z * pdp[u2];
                }
                *(float4*)(det1 + db) = make_float4(d[0], d[1], d[2], d[3]);
                *(float4*)(det2 + db) = make_float4(d[0], d[1], d[2], d[3]);
                __half h4[4], l4[4];
                #pragma unroll
                for (int u2 = 0; u2 < 4; u2++) {
                    h4[u2] = __float2half(d[u2]);
                    l4[u2] = __float2half(d[u2] - __half2float(h4[u2]));
                }
                *(uint2*)(g_det_h + db) = *(const uint2*)h4;
                *(uint2*)(g_det_l + db) = *(const uint2*)l4;
            }
        }
        gridbar(++ph, ncta);

        // ---- P2: hidden GEMMs (80 tiles of 128x128) ----
        for (int u = cta; u < 80; u += ncta) {
            const int z = u % 2, v = u / 2;
            const int nb = v % 5, mb = v / 5;
            if (z == 0)
                gemm_tile<2>(g_det_h, g_det_l, g_Wp1, bp1, nullptr,
                             nullptr, g_hp_h, g_hp_l, H_DIM, 1200, 10, mb * 128, nb * 128, 0, 1, smraw);
            else
                gemm_tile<2>(g_det_h, g_det_l, g_Wq1d, bq1,
                             g_genc + (size_t)t * BB * D_DIM,
                             nullptr, g_hq_h, g_hq_l, H_DIM, 1200, 10, mb * 128, nb * 128, 0, 1, smraw);
        }
        gridbar(++ph, ncta);

        // ---- P3 combo: heads + dist + rnn(t+1) + gh(t+1) + gi(t+1) ----
        if (cta >= 64 && cta < 144) {
            const int u = cta - 64;
            const int z = u % 2, v = u / 2;
            const int sl = v % KSPLIT, mb = v / KSPLIT;
            const __half* Ah = z ? g_hq_h : g_hp_h;
            const __half* Al = z ? g_hq_l : g_hp_l;
            const __half* Wp = z ? g_Wq2 : g_Wp2;
            float* Cf = g_hpart + (size_t)(z * KSPLIT + sl) * BB * 64;
            gemm_tile<1>(Ah, Al, Wp, nullptr, nullptr, Cf, nullptr, nullptr,
                         64, 1200, 2, mb * 128, 0, sl * 256, 0, smraw);
            __threadfence();
            __syncthreads();
            if (tid == 0) atomicAdd(&g_hcnt, 1);
        }
        if (cta >= 72 && !last) {
            for (int u = cta - 72; u < 120; u += ncta - 72) gh_tile(u, b_hh, smraw);
        }
        if (cta < 64) {
            cnt_wait(&g_hcnt, hbase + 80u * (unsigned)(t + 1));
            const int b0 = cta * 16;
            const float* ep = noise_p + (size_t)t * BB * S_DIM;
            const float* eq = noise_q + (size_t)t * BB * S_DIM;
            float* pm_o = out + OFF_PM    + (size_t)t * BB * S_DIM;
            float* ps_o = out + OFF_PS    + (size_t)t * BB * S_DIM;
            float* pr_o = out + OFF_PRIOR + (size_t)t * BB * S_DIM;
            float* qm_o = out + OFF_QM    + (size_t)t * BB * S_DIM;
            float* qs_o = out + OFF_QS    + (size_t)t * BB * S_DIM;
            float* po_o = out + OFF_POST  + (size_t)t * BB * S_DIM;
            for (int i = tid; i < 16 * S_DIM; i += 256) {
                const int r = i >> 5, sx = i & 31;
                const int b = b0 + r;
                float pm = bp2[sx], pr2 = bp2[32 + sx];
                float qm = bq2[sx], qr2 = bq2[32 + sx];
                #pragma unroll
                for (int sl = 0; sl < KSPLIT; sl++) {
                    const size_t a0 = ((size_t)sl * BB + b) * 64;
                    const size_t a1 = ((size_t)(KSPLIT + sl) * BB + b) * 64;
                    pm  += __ldcg(&g_hpart[a0 + sx]);
                    pr2 += __ldcg(&g_hpart[a0 + 32 + sx]);
                    qm  += __ldcg(&g_hpart[a1 + sx]);
                    qr2 += __ldcg(&g_hpart[a1 + 32 + sx]);
                }
                const float ps = softplusf_(pr2) + MIN_STD;
                const float qs = softplusf_(qr2) + MIN_STD;
                const size_t gidx = (size_t)b * S_DIM + sx;
                pm_o[gidx] = pm; ps_o[gidx] = ps; pr_o[gidx] = fmaf(ps, ep[gidx], pm);
                qm_o[gidx] = qm; qs_o[gidx] = qs;
                const float post = fmaf(qs, eq[gidx], qm);
                po_o[gidx] = post;
                s_in[r][6 + sx] = post;
            }
            if (!last) {
                const float* act1 = actions + (size_t)(t + 1) * BB * A_DIM;
                for (int i = tid; i < 16 * A_DIM; i += 256) {
                    const int r = i / A_DIM, k = i % A_DIM;
                    s_in[r][k] = act1[(size_t)(b0 + r) * A_DIM + k];
                }
                __syncthreads();
                rnn_compute(b0, W_in, b_in, s_in, s_hi, s_lo);
                __threadfence();
                __syncthreads();
                if (tid == 0) atomicAdd(&g_rcnt, 1);
                cnt_wait(&g_rcnt, rbase + 64u * (unsigned)(t + 1));
                gi_tile(cta, b_ih, smraw);               // tiles 0..63
            }
        } else if (!last) {
            // gi(t+1): tiles 64..119 over CTAs >=144
            if (cta >= 144) {
                const int giu = 64 + (cta - 144);
                if (giu < 120) {
                    cnt_wait(&g_rcnt, rbase + 64u * (unsigned)(t + 1));
                    for (int u = giu; u < 120; u += ncta - 144) gi_tile(u, b_ih, smraw);
                }
            }
        }
        gridbar(++ph, ncta);
    }
}

// ---------------- standalone genc precompute GEMM ----------------
__global__ void __launch_bounds__(256, 2)
genc_gemm()
{
    extern __shared__ char smraw[];
    gemm_tile<2>(g_enc_h, g_enc_l, g_Wq1e, nullptr, nullptr,
                 g_genc, nullptr, nullptr, H_DIM, 2048, 16,
                 blockIdx.y * 128, blockIdx.x * 128, 0, 0, smraw);
}

// ---------------- prep kernels ----------------
__global__ void wprep_w(const float* __restrict__ src, int pitch, int c0, int rows, int K,
                        __half* __restrict__ w)
{
    const int total = rows * K;
    for (int i = blockIdx.x * blockDim.x + threadIdx.x; i < total; i += gridDim.x * blockDim.x)
        w[i] = __float2half(src[(size_t)(i / K) * pitch + c0 + (i % K)]);
}
__global__ void wprep_a(const float* __restrict__ src, int pitch, int c0, int rows, int K,
                        __half* __restrict__ hi, __half* __restrict__ lo)
{
    const int total = rows * K;
    for (int i = blockIdx.x * blockDim.x + threadIdx.x; i < total; i += gridDim.x * blockDim.x) {
        const float v = src[(size_t)(i / K) * pitch + c0 + (i % K)];
        const __half h = __float2half(v);
        hi[i] = h;
        lo[i] = __float2half(v - __half2float(h));
    }
}

// ---------------- host launcher ----------------
extern "C" void kernel_launch(void* const* d_in, const int* in_sizes, int n_in,
                              void* d_out, int out_size) {
    const float* encoded    = (const float*)d_in[1];
    const float* actions    = (const float*)d_in[2];
    const float* init_stoch = (const float*)d_in[3];
    const float* init_det   = (const float*)d_in[4];
    const float* noise_p    = (const float*)d_in[5];
    const float* noise_q    = (const float*)d_in[6];
    const float* W_in = (const float*)d_in[7];
    const float* b_in = (const float*)d_in[8];
    const float* W_ih = (const float*)d_in[9];
    const float* W_hh = (const float*)d_in[10];
    const float* b_ih = (const float*)d_in[11];
    const float* b_hh = (const float*)d_in[12];
    const float* Wp1  = (const float*)d_in[13];
    const float* bp1  = (const float*)d_in[14];
    const float* Wp2  = (const float*)d_in[15];
    const float* bp2  = (const float*)d_in[16];
    const float* Wq1  = (const float*)d_in[17];
    const float* bq1  = (const float*)d_in[18];
    const float* Wq2  = (const float*)d_in[19];
    const float* bq2  = (const float*)d_in[20];
    float* out = (float*)d_out;

    __half *Wih, *Whh, *Wp1h, *Wq1dh, *Wq1eh, *Wp2h, *Wq2h;
    __half *enc_h, *enc_l, *det_h, *det_l;
    cudaGetSymbolAddress((void**)&Wih, g_Wih);
    cudaGetSymbolAddress((void**)&Whh, g_Whh);
    cudaGetSymbolAddress((void**)&Wp1h, g_Wp1);
    cudaGetSymbolAddress((void**)&Wq1dh, g_Wq1d);
    cudaGetSymbolAddress((void**)&Wq1eh, g_Wq1e);
    cudaGetSymbolAddress((void**)&Wp2h, g_Wp2);
    cudaGetSymbolAddress((void**)&Wq2h, g_Wq2);
    cudaGetSymbolAddress((void**)&enc_h, g_enc_h);
    cudaGetSymbolAddress((void**)&enc_l, g_enc_l);
    cudaGetSymbolAddress((void**)&det_h, g_det_h);
    cudaGetSymbolAddress((void**)&det_l, g_det_l);

    cudaFuncSetAttribute(genc_gemm, cudaFuncAttributeMaxDynamicSharedMemorySize, SMEM_GEMM);
    cudaFuncSetAttribute(rssm_rollout, cudaFuncAttributeMaxDynamicSharedMemorySize, SMEM_GEMM);

    int sms = 148;
    cudaDeviceGetAttribute(&sms, cudaDevAttrMultiProcessorCount, 0);
    int ncta = 2 * sms;
    if (ncta > MAXCTA) ncta = MAXCTA;
    if (ncta < 224) ncta = 224;

    // ---- once-per-replay prep ----
    wprep_w<<<4096, 256>>>(W_ih, D_DIM, 0, G3_DIM, D_DIM, Wih);
    wprep_w<<<4096, 256>>>(W_hh, D_DIM, 0, G3_DIM, D_DIM, Whh);
    wprep_w<<<2048, 256>>>(Wp1, D_DIM, 0, H_DIM, D_DIM, Wp1h);
    wprep_w<<<2048, 256>>>(Wq1, D_DIM + E_DIM, 0, H_DIM, D_DIM, Wq1dh);
    wprep_w<<<2048, 256>>>(Wq1, D_DIM + E_DIM, D_DIM, H_DIM, E_DIM, Wq1eh);
    wprep_w<<<256, 256>>>(Wp2, H_DIM, 0, 64, H_DIM, Wp2h);
    wprep_w<<<256, 256>>>(Wq2, H_DIM, 0, 64, H_DIM, Wq2h);
    wprep_a<<<16384, 256>>>(encoded, E_DIM, 0, T_STEPS * BB, E_DIM, enc_h, enc_l);
    wprep_a<<<2048, 256>>>(init_det, D_DIM, 0, BB, D_DIM, det_h, det_l);

    // ---- genc = encoded @ Wq1[:,600:]^T ----
    genc_gemm<<<dim3(5, T_STEPS * BB / BMT, 1), 256, SMEM_GEMM>>>();

    // ---- persistent rollout ----
    rssm_rollout<<<ncta, 256, SMEM_GEMM>>>(
        actions, init_stoch, init_det, noise_p, noise_q,
        W_in, b_in, b_ih, b_hh, bp1, bq1, bp2, bq2, out, ncta);
}

// round 15
// speedup vs baseline: 1.3582x; 1.3582x over previous
#include <cuda_runtime.h>
#include <cuda_fp16.h>
#include <math.h>
#include <stdint.h>

#define T_STEPS 50
#define BB      1024
#define S_DIM   32
#define D_DIM   600
#define H_DIM   600
#define A_DIM   6
#define E_DIM   1024
#define G3_DIM  1800
#define MIN_STD 0.1f
#define KSPLIT  5
#define MAXCTA  304

#define SZ_SB   ((size_t)T_STEPS * BB * S_DIM)
#define SZ_DB   ((size_t)T_STEPS * BB * D_DIM)
#define OFF_PM    ((size_t)0)
#define OFF_PS    (SZ_SB)
#define OFF_PRIOR (2 * SZ_SB)
#define OFF_DET1  (3 * SZ_SB)
#define OFF_QM    (3 * SZ_SB + SZ_DB)
#define OFF_QS    (4 * SZ_SB + SZ_DB)
#define OFF_POST  (5 * SZ_SB + SZ_DB)
#define OFF_DET2  (6 * SZ_SB + SZ_DB)

// ---------------- static device scratch ----------------
__device__ __half g_Wih[G3_DIM * D_DIM];
__device__ __half g_Whh[G3_DIM * D_DIM];
__device__ __half g_Wp1[H_DIM * D_DIM];
__device__ __half g_Wq1d[H_DIM * D_DIM];
__device__ __half g_Wq1e[H_DIM * E_DIM];
__device__ __half g_Wp2[64 * H_DIM];
__device__ __half g_Wq2[64 * H_DIM];
__device__ __half g_enc_h[(size_t)T_STEPS * BB * E_DIM];
__device__ __half g_enc_l[(size_t)T_STEPS * BB * E_DIM];
__device__ float  g_genc[(size_t)T_STEPS * BB * D_DIM];
__device__ __half g_rnn_h[BB * H_DIM], g_rnn_l[BB * H_DIM];
__device__ __half g_det_h[BB * D_DIM], g_det_l[BB * D_DIM];
__device__ __half g_hp_h [BB * H_DIM], g_hp_l [BB * H_DIM];
__device__ __half g_hq_h [BB * H_DIM], g_hq_l [BB * H_DIM];
__device__ float g_gi[BB * G3_DIM], g_gh[BB * G3_DIM];
__device__ float g_hpart[2 * KSPLIT * BB * 64];

__device__ volatile unsigned g_flags[MAXCTA];
__device__ volatile unsigned g_go;
__device__ unsigned g_hcnt;

__device__ __forceinline__ float eluf(float x)      { return x > 0.f ? x : expm1f(x); }
__device__ __forceinline__ float sigmoidf_(float x) { return 1.f / (1.f + expf(-x)); }
__device__ __forceinline__ float softplusf_(float x){ return fmaxf(x, 0.f) + log1pf(expf(-fabsf(x))); }

// ---------------- PTX helpers ----------------
__device__ __forceinline__ uint32_t smem_u32(const void* p) {
    uint32_t a;
    asm("{ .reg .u64 t; cvta.to.shared.u64 t, %1; cvt.u32.u64 %0, t; }" : "=r"(a) : "l"(p));
    return a;
}
__device__ __forceinline__ void cpa16(uint32_t dst, const void* src, int nb) {
    asm volatile("cp.async.cg.shared.global [%0], [%1], 16, %2;" :: "r"(dst), "l"(src), "r"(nb));
}
#define CP_COMMIT() asm volatile("cp.async.commit_group;" ::: "memory")

__device__ __forceinline__ void ldsm4(uint32_t* r, uint32_t addr) {
    asm volatile("ldmatrix.sync.aligned.m8n8.x4.shared.b16 {%0,%1,%2,%3}, [%4];"
        : "=r"(r[0]), "=r"(r[1]), "=r"(r[2]), "=r"(r[3]) : "r"(addr));
}
__device__ __forceinline__ void mma16816(float* d, const uint32_t* a, const uint32_t* b) {
    asm volatile("mma.sync.aligned.m16n8k16.row.col.f32.f16.f16.f32 "
        "{%0,%1,%2,%3}, {%4,%5,%6,%7}, {%8,%9}, {%0,%1,%2,%3};"
        : "+f"(d[0]), "+f"(d[1]), "+f"(d[2]), "+f"(d[3])
        : "r"(a[0]), "r"(a[1]), "r"(a[2]), "r"(a[3]), "r"(b[0]), "r"(b[1]));
}

// ---------------- grid barrier ----------------
__device__ __forceinline__ void gridbar(unsigned ph, int ncta) {
    __threadfence();
    __syncthreads();
    if (threadIdx.x == 0) g_flags[blockIdx.x] = ph;
    if (blockIdx.x == 0) {
        for (int c = threadIdx.x; c < ncta; c += 256)
            while (g_flags[c] < ph) { }
        __syncthreads();
        if (threadIdx.x == 0) { __threadfence(); g_go = ph; }
        __syncthreads();
    } else {
        if (threadIdx.x == 0) { while (g_go < ph) { } }
        __syncthreads();
    }
}

// ---------------- GEMM tile: 2-term fp16, de-chained term passes ----------------
#define BMT 128
#define BNT 64
#define RSB 144
#define ASZ (BMT * RSB)               // 18432
#define WSZ (BNT * RSB)               // 9216
#define STG (2 * ASZ + WSZ)           // 46080
#define SMEM_GEMM (2 * STG)           // 92160

__device__ __forceinline__ void gemm_tile(
    const __half* Ahi, const __half* Alo, const __half* W,
    const float* bias, const float* extra,
    float* Cf, __half* Chi, __half* Clo,
    int N, int Kb, int KC, int m0, int n0, int koff, int elu, char* smraw)
{
    const int tid = threadIdx.x;
    const uint32_t sb = smem_u32(smraw);
    const int wid = tid >> 5, lane = tid & 31;
    const int wm = wid & 3, wn = wid >> 2;
    const int arow  = lane & 15;
    const int akoff = (lane >> 4) * 16;
    const int brow  = (lane & 7) + ((lane >> 4) << 3);
    const int bkoff = ((lane >> 3) & 1) * 16;

    float acc[2][4][4];
#pragma unroll
    for (int i = 0; i < 2; i++)
#pragma unroll
        for (int j = 0; j < 4; j++)
#pragma unroll
            for (int q = 0; q < 4; q++) acc[i][j][q] = 0.f;

    auto load_stage = [&](int kc) {
        const uint32_t base = sb + (uint32_t)(kc & 1) * STG;
        const int k0b = koff + kc * 128;
        #pragma unroll
        for (int v = 0; v < 8; v++) {
            const int idx  = v * 256 + tid;
            const int half = idx >> 10, r = (idx >> 3) & 127, j = idx & 7;
            const int off  = k0b + j * 16;
            const char* src = (const char*)(half ? Alo : Ahi);
            const int nb = (off + 16 <= Kb) ? 16 : 0;
            const char* p = nb ? src + (size_t)(m0 + r) * Kb + off : src;
            cpa16(base + half * ASZ + r * RSB + j * 16, p, nb);
        }
        #pragma unroll
        for (int v = 0; v < 2; v++) {
            const int idx  = v * 256 + tid;
            const int r    = (idx >> 3) & 63, j = idx & 7;
            const int off  = k0b + j * 16;
            const int nb = (off + 16 <= Kb && (n0 + r) < N) ? 16 : 0;
            const char* p = nb ? (const char*)W + (size_t)(n0 + r) * Kb + off : (const char*)W;
            cpa16(base + 2 * ASZ + r * RSB + j * 16, p, nb);
        }
        CP_COMMIT();
    };

    load_stage(0);
    for (int kc = 0; kc < KC; kc++) {
        if (kc + 1 < KC) { load_stage(kc + 1); asm volatile("cp.async.wait_group 1;" ::: "memory"); }
        else             {                      asm volatile("cp.async.wait_group 0;" ::: "memory"); }
        __syncthreads();
        const uint32_t base = sb + (uint32_t)(kc & 1) * STG;

        #pragma unroll
        for (int k16 = 0; k16 < 4; k16++) {
            uint32_t a_h[2][4], a_l[2][4], b[2][4];
            const uint32_t Ah0 = base + (wm * 32 + arow) * RSB + k16 * 32 + akoff;
            ldsm4(a_h[0], Ah0);           ldsm4(a_h[1], Ah0 + 16 * RSB);
            ldsm4(a_l[0], Ah0 + ASZ);     ldsm4(a_l[1], Ah0 + ASZ + 16 * RSB);
            const uint32_t Wh0 = base + 2 * ASZ + (wn * 32 + brow) * RSB + k16 * 32 + bkoff;
            ldsm4(b[0], Wh0);             ldsm4(b[1], Wh0 + 16 * RSB);

            // pass 1: hi-term into all 8 independent quads
            #pragma unroll
            for (int tm = 0; tm < 2; tm++)
                #pragma unroll
                for (int g = 0; g < 2; g++)
                    #pragma unroll
                    for (int sub = 0; sub < 2; sub++)
                        mma16816(acc[tm][g * 2 + sub], a_h[tm], &b[g][sub * 2]);
            // pass 2: lo-term (re-use distance 8 MMAs -> RAW latency hidden)
            #pragma unroll
            for (int tm = 0; tm < 2; tm++)
                #pragma unroll
                for (int g = 0; g < 2; g++)
                    #pragma unroll
                    for (int sub = 0; sub < 2; sub++)
                        mma16816(acc[tm][g * 2 + sub], a_l[tm], &b[g][sub * 2]);
        }
        __syncthreads();
    }

    #pragma unroll
    for (int nt = 0; nt < 4; nt++) {
        const int gc = n0 + wn * 32 + nt * 8 + ((lane & 3) << 1);
        if (gc >= N) continue;
        const float b0 = bias ? bias[gc]     : 0.f;
        const float b1 = bias ? bias[gc + 1] : 0.f;
        #pragma unroll
        for (int tm = 0; tm < 2; tm++) {
            const int r0 = m0 + wm * 32 + tm * 16 + (lane >> 2);
            #pragma unroll
            for (int hh = 0; hh < 2; hh++) {
                const int gr = r0 + hh * 8;
                float v0 = acc[tm][nt][hh * 2 + 0] + b0;
                float v1 = acc[tm][nt][hh * 2 + 1] + b1;
                if (extra) {
                    v0 += extra[(size_t)gr * N + gc];
                    v1 += extra[(size_t)gr * N + gc + 1];
                }
                if (elu) { v0 = eluf(v0); v1 = eluf(v1); }
                if (Cf) {
                    Cf[(size_t)gr * N + gc]     = v0;
                    Cf[(size_t)gr * N + gc + 1] = v1;
                }
                if (Chi) {
                    const __half h0 = __float2half(v0);
                    const __half h1 = __float2half(v1);
                    Chi[(size_t)gr * N + gc]     = h0;
                    Chi[(size_t)gr * N + gc + 1] = h1;
                    Clo[(size_t)gr * N + gc]     = __float2half(v0 - __half2float(h0));
                    Clo[(size_t)gr * N + gc + 1] = __float2half(v1 - __half2float(h1));
                }
            }
        }
    }
}

// ---------------- rnn compute ----------------
__device__ void rnn_compute(int b0, const float* __restrict__ W_in, const float* __restrict__ b_in,
                            float (*s_in)[38], __half* s_hi, __half* s_lo)
{
    const int tid = threadIdx.x;
    for (int h = tid; h < H_DIM; h += 256) {
        float w[38];
        #pragma unroll
        for (int k = 0; k < 38; k++) w[k] = W_in[h * 38 + k];
        const float bias = b_in[h];
        #pragma unroll 4
        for (int b = 0; b < 16; b++) {
            float acc = bias;
            #pragma unroll
            for (int k = 0; k < 38; k++) acc = fmaf(s_in[b][k], w[k], acc);
            const float v = eluf(acc);
            const __half hh = __float2half(v);
            s_hi[b * 600 + h] = hh;
            s_lo[b * 600 + h] = __float2half(v - __half2float(hh));
        }
    }
    __syncthreads();
    const size_t gbase = (size_t)b0 * H_DIM;
    for (int i = tid; i < 16 * 600; i += 256) {
        g_rnn_h[gbase + i] = s_hi[i];
        g_rnn_l[gbase + i] = s_lo[i];
    }
}

// ---------------- gh tile schedule ----------------
__device__ __forceinline__ void gh_tiles(int cta, int ncta, const float* b_hh, char* smraw) {
    for (int u = cta - 64; u < 232; u += ncta - 64) {
        const int mb = u / 29, nb = u % 29;
        gemm_tile(g_det_h, g_det_l, g_Whh, b_hh, nullptr,
                  g_gh, nullptr, nullptr, G3_DIM, 1200, 10, mb * 128, nb * 64, 0, 0, smraw);
    }
}

// ---------------- persistent rollout kernel ----------------
__global__ void __launch_bounds__(256, 2)
rssm_rollout(const float* __restrict__ actions, const float* __restrict__ init_stoch,
             const float* __restrict__ init_det,
             const float* __restrict__ noise_p, const float* __restrict__ noise_q,
             const float* __restrict__ W_in, const float* __restrict__ b_in,
             const float* __restrict__ b_ih, const float* __restrict__ b_hh,
             const float* __restrict__ bp1, const float* __restrict__ bq1,
             const float* __restrict__ bp2, const float* __restrict__ bq2,
             float* __restrict__ out, int ncta)
{
    extern __shared__ char smraw[];
    const int cta = blockIdx.x, tid = threadIdx.x;
    unsigned ph = g_go;
    const unsigned hbase = *(volatile unsigned*)&g_hcnt;

    float (*s_in)[38] = (float(*)[38])smraw;
    __half* s_hi = (__half*)(smraw + 4096);
    __half* s_lo = (__half*)(smraw + 4096 + 19200);

    // ---- preamble: rnn(0) on CTAs<64; gh(0) on CTAs>=64 ----
    if (cta < 64) {
        const int b0 = cta * 16;
        for (int i = tid; i < 16 * 38; i += 256) {
            const int r = i / 38, k = i % 38;
            s_in[r][k] = (k < 6) ? actions[(size_t)(b0 + r) * A_DIM + k]
                                 : init_stoch[(size_t)(b0 + r) * S_DIM + (k - 6)];
        }
        __syncthreads();
        rnn_compute(b0, W_in, b_in, s_in, s_hi, s_lo);
    } else {
        gh_tiles(cta, ncta, b_hh, smraw);
    }
    gridbar(++ph, ncta);

    for (int t = 0; t < T_STEPS; t++) {
        // ---- P1: gi tiles (232) ----
        for (int u = cta; u < 232; u += ncta) {
            const int mb = u / 29, nb = u % 29;
            gemm_tile(g_rnn_h, g_rnn_l, g_Wih, b_ih, nullptr,
                      g_gi, nullptr, nullptr, G3_DIM, 1200, 10, mb * 128, nb * 64, 0, 0, smraw);
        }
        gridbar(++ph, ncta);

        // ---- P2: GRU gates ----
        {
            const float* det_prev = (t == 0) ? init_det : out + OFF_DET1 + (size_t)(t - 1) * BB * D_DIM;
            float* det1 = out + OFF_DET1 + (size_t)t * BB * D_DIM;
            float* det2 = out + OFF_DET2 + (size_t)t * BB * D_DIM;
            for (int q = cta * 256 + tid; q < BB * 150; q += ncta * 256) {
                const int b = q / 150, jq = (q % 150) * 4;
                const size_t gb = (size_t)b * G3_DIM + jq;
                const float4 ir = __ldcg((const float4*)(g_gi + gb));
                const float4 iz = __ldcg((const float4*)(g_gi + gb + D_DIM));
                const float4 in = __ldcg((const float4*)(g_gi + gb + 2 * D_DIM));
                const float4 hr = __ldcg((const float4*)(g_gh + gb));
                const float4 hz = __ldcg((const float4*)(g_gh + gb + D_DIM));
                const float4 hn = __ldcg((const float4*)(g_gh + gb + 2 * D_DIM));
                const size_t db = (size_t)b * D_DIM + jq;
                const float4 dp = __ldcg((const float4*)(det_prev + db));
                const float* pir = &ir.x; const float* piz = &iz.x; const float* pin = &in.x;
                const float* phr = &hr.x; const float* phz = &hz.x; const float* phn = &hn.x;
                const float* pdp = &dp.x;
                float d[4];
                #pragma unroll
                for (int u2 = 0; u2 < 4; u2++) {
                    const float r = sigmoidf_(pir[u2] + phr[u2]);
                    const float z = sigmoidf_(piz[u2] + phz[u2]);
                    const float n = tanhf(pin[u2] + r * phn[u2]);
                    d[u2] = (1.f - z) * n + z * pdp[u2];
                }
                *(float4*)(det1 + db) = make_float4(d[0], d[1], d[2], d[3]);
                *(float4*)(det2 + db) = make_float4(d[0], d[1], d[2], d[3]);
                __half h4[4], l4[4];
                #pragma unroll
                for (int u2 = 0; u2 < 4; u2++) {
                    h4[u2] = __float2half(d[u2]);
                    l4[u2] = __float2half(d[u2] - __half2float(h4[u2]));
                }
                *(uint2*)(g_det_h + db) = *(const uint2*)h4;
                *(uint2*)(g_det_l + db) = *(const uint2*)l4;
            }
        }
        gridbar(++ph, ncta);

        // ---- P3: hidden GEMMs (160 tiles) ----
        for (int u = cta; u < 160; u += ncta) {
            const int z = u % 2, v = u / 2;
            const int nb = v % 10, mb = v / 10;
            if (z == 0)
                gemm_tile(g_det_h, g_det_l, g_Wp1, bp1, nullptr,
                          nullptr, g_hp_h, g_hp_l, H_DIM, 1200, 10, mb * 128, nb * 64, 0, 1, smraw);
            else
                gemm_tile(g_det_h, g_det_l, g_Wq1d, bq1,
                          g_genc + (size_t)t * BB * D_DIM,
                          nullptr, g_hq_h, g_hq_l, H_DIM, 1200, 10, mb * 128, nb * 64, 0, 1, smraw);
        }
        gridbar(++ph, ncta);

        // ---- P4+P5 combo ----
        const int last = (t + 1 == T_STEPS);
        if (cta >= 64 && cta < 144) {
            const int u = cta - 64;
            const int z = u % 2, v = u / 2;
            const int sl = v % KSPLIT, mb = v / KSPLIT;
            const __half* Ah = z ? g_hq_h : g_hp_h;
            const __half* Al = z ? g_hq_l : g_hp_l;
            const __half* Wp = z ? g_Wq2 : g_Wp2;
            float* Cf = g_hpart + (size_t)(z * KSPLIT + sl) * BB * 64;
            gemm_tile(Ah, Al, Wp, nullptr, nullptr, Cf, nullptr, nullptr,
                      64, 1200, 2, mb * 128, 0, sl * 256, 0, smraw);
            __threadfence();
            __syncthreads();
            if (tid == 0) atomicAdd(&g_hcnt, 1);
        }
        if (cta >= 72 && !last) {
            gh_tiles(cta, ncta, b_hh, smraw);
        }
        if (cta < 64) {
            if (tid == 0) {
                const unsigned target = hbase + 80u * (unsigned)(t + 1);
                while (*(volatile unsigned*)&g_hcnt < target) { }
            }
            __syncthreads();
            __threadfence();
            const int b0 = cta * 16;
            const float* ep = noise_p + (size_t)t * BB * S_DIM;
            const float* eq = noise_q + (size_t)t * BB * S_DIM;
            float* pm_o = out + OFF_PM    + (size_t)t * BB * S_DIM;
            float* ps_o = out + OFF_PS    + (size_t)t * BB * S_DIM;
            float* pr_o = out + OFF_PRIOR + (size_t)t * BB * S_DIM;
            float* qm_o = out + OFF_QM    + (size_t)t * BB * S_DIM;
            float* qs_o = out + OFF_QS    + (size_t)t * BB * S_DIM;
            float* po_o = out + OFF_POST  + (size_t)t * BB * S_DIM;
            for (int i = tid; i < 16 * S_DIM; i += 256) {
                const int r = i >> 5, sx = i & 31;
                const int b = b0 + r;
                float pm = bp2[sx], pr2 = bp2[32 + sx];
                float qm = bq2[sx], qr2 = bq2[32 + sx];
                #pragma unroll
                for (int sl = 0; sl < KSPLIT; sl++) {
                    const size_t a0 = ((size_t)sl * BB + b) * 64;
                    const size_t a1 = ((size_t)(KSPLIT + sl) * BB + b) * 64;
                    pm  += __ldcg(&g_hpart[a0 + sx]);
                    pr2 += __ldcg(&g_hpart[a0 + 32 + sx]);
                    qm  += __ldcg(&g_hpart[a1 + sx]);
                    qr2 += __ldcg(&g_hpart[a1 + 32 + sx]);
                }
                const float ps = softplusf_(pr2) + MIN_STD;
                const float qs = softplusf_(qr2) + MIN_STD;
                const size_t gidx = (size_t)b * S_DIM + sx;
                pm_o[gidx] = pm; ps_o[gidx] = ps; pr_o[gidx] = fmaf(ps, ep[gidx], pm);
                qm_o[gidx] = qm; qs_o[gidx] = qs;
                const float post = fmaf(qs, eq[gidx], qm);
                po_o[gidx] = post;
                s_in[r][6 + sx] = post;
            }
            if (!last) {
                const float* act1 = actions + (size_t)(t + 1) * BB * A_DIM;
                for (int i = tid; i < 16 * A_DIM; i += 256) {
                    const int r = i / A_DIM, k = i % A_DIM;
                    s_in[r][k] = act1[(size_t)(b0 + r) * A_DIM + k];
                }
                __syncthreads();
                rnn_compute(b0, W_in, b_in, s_in, s_hi, s_lo);
            }
        }
        gridbar(++ph, ncta);
    }
}

// ---------------- standalone genc precompute GEMM ----------------
__global__ void __launch_bounds__(256, 2)
genc_gemm()
{
    extern __shared__ char smraw[];
    gemm_tile(g_enc_h, g_enc_l, g_Wq1e, nullptr, nullptr,
              g_genc, nullptr, nullptr, H_DIM, 2048, 16,
              blockIdx.y * 128, blockIdx.x * 64, 0, 0, smraw);
}

// ---------------- prep kernels ----------------
__global__ void wprep_w(const float* __restrict__ src, int pitch, int c0, int rows, int K,
                        __half* __restrict__ w)
{
    const int total = rows * K;
    for (int i = blockIdx.x * blockDim.x + threadIdx.x; i < total; i += gridDim.x * blockDim.x)
        w[i] = __float2half(src[(size_t)(i / K) * pitch + c0 + (i % K)]);
}
__global__ void wprep_a(const float* __restrict__ src, int pitch, int c0, int rows, int K,
                        __half* __restrict__ hi, __half* __restrict__ lo)
{
    const int total = rows * K;
    for (int i = blockIdx.x * blockDim.x + threadIdx.x; i < total; i += gridDim.x * blockDim.x) {
        const float v = src[(size_t)(i / K) * pitch + c0 + (i % K)];
        const __half h = __float2half(v);
        hi[i] = h;
        lo[i] = __float2half(v - __half2float(h));
    }
}

// ---------------- host launcher ----------------
extern "C" void kernel_launch(void* const* d_in, const int* in_sizes, int n_in,
                              void* d_out, int out_size) {
    const float* encoded    = (const float*)d_in[1];
    const float* actions    = (const float*)d_in[2];
    const float* init_stoch = (const float*)d_in[3];
    const float* init_det   = (const float*)d_in[4];
    const float* noise_p    = (const float*)d_in[5];
    const float* noise_q    = (const float*)d_in[6];
    const float* W_in = (const float*)d_in[7];
    const float* b_in = (const float*)d_in[8];
    const float* W_ih = (const float*)d_in[9];
    const float* W_hh = (const float*)d_in[10];
    const float* b_ih = (const float*)d_in[11];
    const float* b_hh = (const float*)d_in[12];
    const float* Wp1  = (const float*)d_in[13];
    const float* bp1  = (const float*)d_in[14];
    const float* Wp2  = (const float*)d_in[15];
    const float* bp2  = (const float*)d_in[16];
    const float* Wq1  = (const float*)d_in[17];
    const float* bq1  = (const float*)d_in[18];
    const float* Wq2  = (const float*)d_in[19];
    const float* bq2  = (const float*)d_in[20];
    float* out = (float*)d_out;

    __half *Wih, *Whh, *Wp1h, *Wq1dh, *Wq1eh, *Wp2h, *Wq2h;
    __half *enc_h, *enc_l, *det_h, *det_l;
    cudaGetSymbolAddress((void**)&Wih, g_Wih);
    cudaGetSymbolAddress((void**)&Whh, g_Whh);
    cudaGetSymbolAddress((void**)&Wp1h, g_Wp1);
    cudaGetSymbolAddress((void**)&Wq1dh, g_Wq1d);
    cudaGetSymbolAddress((void**)&Wq1eh, g_Wq1e);
    cudaGetSymbolAddress((void**)&Wp2h, g_Wp2);
    cudaGetSymbolAddress((void**)&Wq2h, g_Wq2);
    cudaGetSymbolAddress((void**)&enc_h, g_enc_h);
    cudaGetSymbolAddress((void**)&enc_l, g_enc_l);
    cudaGetSymbolAddress((void**)&det_h, g_det_h);
    cudaGetSymbolAddress((void**)&det_l, g_det_l);

    cudaFuncSetAttribute(genc_gemm, cudaFuncAttributeMaxDynamicSharedMemorySize, SMEM_GEMM);
    cudaFuncSetAttribute(rssm_rollout, cudaFuncAttributeMaxDynamicSharedMemorySize, SMEM_GEMM);

    int sms = 148;
    cudaDeviceGetAttribute(&sms, cudaDevAttrMultiProcessorCount, 0);
    int ncta = 2 * sms;
    if (ncta > MAXCTA) ncta = MAXCTA;
    if (ncta < 224) ncta = 224;

    // ---- once-per-replay prep ----
    wprep_w<<<4096, 256>>>(W_ih, D_DIM, 0, G3_DIM, D_DIM, Wih);
    wprep_w<<<4096, 256>>>(W_hh, D_DIM, 0, G3_DIM, D_DIM, Whh);
    wprep_w<<<2048, 256>>>(Wp1, D_DIM, 0, H_DIM, D_DIM, Wp1h);
    wprep_w<<<2048, 256>>>(Wq1, D_DIM + E_DIM, 0, H_DIM, D_DIM, Wq1dh);
    wprep_w<<<2048, 256>>>(Wq1, D_DIM + E_DIM, D_DIM, H_DIM, E_DIM, Wq1eh);
    wprep_w<<<256, 256>>>(Wp2, H_DIM, 0, 64, H_DIM, Wp2h);
    wprep_w<<<256, 256>>>(Wq2, H_DIM, 0, 64, H_DIM, Wq2h);
    wprep_a<<<16384, 256>>>(encoded, E_DIM, 0, T_STEPS * BB, E_DIM, enc_h, enc_l);
    wprep_a<<<2048, 256>>>(init_det, D_DIM, 0, BB, D_DIM, det_h, det_l);

    // ---- genc = encoded @ Wq1[:,600:]^T ----
    genc_gemm<<<dim3(10, T_STEPS * BB / BMT, 1), 256, SMEM_GEMM>>>();

    // ---- persistent rollout ----
    rssm_rollout<<<ncta, 256, SMEM_GEMM>>>(
        actions, init_stoch, init_det, noise_p, noise_q,
        W_in, b_in, b_ih, b_hh, bp1, bq1, bp2, bq2, out, ncta);
}